// round 13
// baseline (speedup 1.0000x reference)
#include <cuda_runtime.h>

// Problem constants
#define BB      1024
#define NPATCH  64
#define PD      192
#define KCODES  4096
#define EDIM    2048
#define VDIM    2048
#define M_TOTAL (BB * NPATCH)   // 65536 patches

// Output layout (concatenated, float32)
#define O_ZREAL 0
#define O_ZVSA  (BB * EDIM)
#define O_IDX   (O_ZVSA + BB * VDIM)
#define O_ZLOC  (O_IDX + BB * NPATCH)

__device__ int g_indices[M_TOTAL];

// ---------------------------------------------------------------------------
// Fused patchify + GEMM + argmax, 512 threads (16 warps -> occ 25%).
//
// Block tile: 128 patches (2 images) x 256 codes per iteration, all 4096.
// Threads (ty,tx) = 16 x 32; warp == one ty row (tx = lane).
//   patches: ty + 16i, i<8
//   codes:   4 f32x2 slots, pair index s = tx + 32j, codes {2s, 2s+1}
// acc[8][4] packed f32x2 (exact fp32 per lane, ascending-k accumulation).
// A broadcast across the warp (1 LDS.32/value); B LDS.64 two-phase
// conflict-free; staging banks c + 8*k4 + 2u cover 0..31.
// Double-buffered Bs: one __syncthreads() per chunk (race-freedom proof in
// R7 commit message; unchanged).
// Argmax cross-thread reduce = full-warp shuffle (no smem).
// ---------------------------------------------------------------------------
#define THREADS 512
#define TM 128
#define TN 256
#define KC 16
#define NCT     (KCODES / TN)    // 16 code tiles
#define KCHUNKS (PD / KC)        // 12 k chunks

#define AS_STRIDE 129            // [192][129] floats
#define BS_STRIDE 258            // 16 rows x (128 float2 + pad)

#define AS_FLOATS (PD * AS_STRIDE)     // 24768
#define BS_FLOATS (KC * BS_STRIDE)     // 4128 per buffer, x2
#define SMEM_BYTES ((AS_FLOATS + 2 * BS_FLOATS) * 4)   // 132096

__device__ __forceinline__ unsigned long long pack2(float lo, float hi) {
    unsigned long long r;
    asm("mov.b64 %0, {%1, %2};" : "=l"(r)
        : "r"(__float_as_uint(lo)), "r"(__float_as_uint(hi)));
    return r;
}
__device__ __forceinline__ void unpack2(unsigned long long v, float& lo, float& hi) {
    unsigned int l, h;
    asm("mov.b64 {%0, %1}, %2;" : "=r"(l), "=r"(h) : "l"(v));
    lo = __uint_as_float(l); hi = __uint_as_float(h);
}
__device__ __forceinline__ void fma2(unsigned long long& d,
                                     unsigned long long a, unsigned long long b) {
    asm("fma.rn.f32x2 %0, %1, %2, %0;" : "+l"(d) : "l"(a), "l"(b));
}

__global__ __launch_bounds__(THREADS, 1)
void argmax_kernel(const float* __restrict__ pixels,
                   const float* __restrict__ codebook,
                   float* __restrict__ out) {
    extern __shared__ float smem[];
    float* As  = smem;
    float* Bs0 = smem + AS_FLOATS;   // double buffer

    const int tid = threadIdx.x;
    const int ty  = tid >> 5;        // 0..15 (warp id)
    const int tx  = tid & 31;        // lane
    const int pb  = blockIdx.x * TM;
    const int b0  = blockIdx.x * 2;

    // B staging decode: chunk = 256 codes x 16 k = 1024 float4, 2/thread.
    // i4 = t*512 + tid ; c = i4>>2 ; k4 = i4&3 ; float index == c (identity).
    int st_c[2], st_k4[2];
#pragma unroll
    for (int t = 0; t < 2; t++) {
        int i4 = t * THREADS + tid;
        st_c[t]  = i4 >> 2;
        st_k4[t] = i4 & 3;
    }

    // ---- Fused patchify: 2 images -> As[d][p].
    // d = ch*64 + (row&7)*8 + (col&7), p = img*64 + (row>>3)*8 + (col>>3).
    {
        const float4* px = (const float4*)(pixels + (size_t)b0 * 3 * 64 * 64);
        for (int i = tid; i < 2 * 3 * 64 * 16; i += THREADS) {   // 6144 float4
            int img = i / 3072;
            int rem = i - img * 3072;
            int ch  = rem >> 10;
            int r2  = rem & 1023;
            int row = r2 >> 4;
            int col0 = (r2 & 15) << 2;
            float4 v = px[i];
            int p = (img << 6) + ((row >> 3) << 3) + (col0 >> 3);
            int d = (ch << 6) + ((row & 7) << 3) + (col0 & 7);
            As[(d + 0) * AS_STRIDE + p] = v.x;
            As[(d + 1) * AS_STRIDE + p] = v.y;
            As[(d + 2) * AS_STRIDE + p] = v.z;
            As[(d + 3) * AS_STRIDE + p] = v.w;
        }
    }

    float bestM[8];
    int   bestI[8];
#pragma unroll
    for (int i = 0; i < 8; i++) { bestM[i] = -1e30f; bestI[i] = 0; }

    __syncthreads();   // As visible before first compute

#pragma unroll 1
    for (int ct = 0; ct < NCT; ct++) {
        const int cb0 = ct * TN;

        unsigned long long acc[8][4];
#pragma unroll
        for (int i = 0; i < 8; i++)
#pragma unroll
            for (int j = 0; j < 4; j++) acc[i][j] = 0ULL;

        float4 ld[2];
#pragma unroll
        for (int t = 0; t < 2; t++)
            ld[t] = *(const float4*)(
                &codebook[(size_t)(cb0 + st_c[t]) * PD + st_k4[t] * 4]);

#pragma unroll 1
        for (int kc = 0; kc < KCHUNKS; kc++) {
            float* Bc = Bs0 + (kc & 1) * BS_FLOATS;
#pragma unroll
            for (int t = 0; t < 2; t++) {
                int base = st_k4[t] * 4 * BS_STRIDE + st_c[t];
                Bc[base + 0 * BS_STRIDE] = ld[t].x;
                Bc[base + 1 * BS_STRIDE] = ld[t].y;
                Bc[base + 2 * BS_STRIDE] = ld[t].z;
                Bc[base + 3 * BS_STRIDE] = ld[t].w;
            }
            __syncthreads();   // single barrier per chunk (double-buffered)

            if (kc + 1 < KCHUNKS) {
#pragma unroll
                for (int t = 0; t < 2; t++)
                    ld[t] = *(const float4*)(
                        &codebook[(size_t)(cb0 + st_c[t]) * PD
                                  + (kc + 1) * KC + st_k4[t] * 4]);
            }

#pragma unroll 4
            for (int kk = 0; kk < KC; kk++) {
                const int krow = kc * KC + kk;
                unsigned long long a2[8], b2[4];
#pragma unroll
                for (int i = 0; i < 8; i++) {
                    float av = As[krow * AS_STRIDE + ty + 16 * i];
                    a2[i] = pack2(av, av);
                }
#pragma unroll
                for (int j = 0; j < 4; j++)
                    b2[j] = *(const unsigned long long*)
                               (&Bc[kk * BS_STRIDE + 2 * (tx + 32 * j)]);
#pragma unroll
                for (int i = 0; i < 8; i++)
#pragma unroll
                    for (int j = 0; j < 4; j++)
                        fma2(acc[i][j], a2[i], b2[j]);
            }
        }

        // Fold tile into running argmax (ascending code order, strict '>').
#pragma unroll
        for (int i = 0; i < 8; i++)
#pragma unroll
            for (int j = 0; j < 4; j++) {
                float lo, hi;
                unpack2(acc[i][j], lo, hi);
                int c0 = cb0 + 2 * (tx + 32 * j);
                if (lo > bestM[i]) { bestM[i] = lo; bestI[i] = c0; }
                if (hi > bestM[i]) { bestM[i] = hi; bestI[i] = c0 + 1; }
            }
    }

    // Cross-lane argmax reduce: warp == one ty row, 32 partials per patch.
    // Lowest index wins exact ties.
#pragma unroll
    for (int i = 0; i < 8; i++) {
        float m  = bestM[i];
        int   bi = bestI[i];
#pragma unroll
        for (int off = 16; off > 0; off >>= 1) {
            float vm = __shfl_down_sync(0xffffffffu, m, off);
            int   vi = __shfl_down_sync(0xffffffffu, bi, off);
            if (vm > m || (vm == m && vi < bi)) { m = vm; bi = vi; }
        }
        if (tx == 0) {
            int p = pb + ty + 16 * i;
            g_indices[p] = bi;
            out[O_IDX + p] = (float)bi;
        }
    }
}

// ---------------------------------------------------------------------------
// z_real = mean of 64 gathered embedding rows; z_local = mean of 9 AGENT rows.
// ---------------------------------------------------------------------------
__global__ void means_kernel(const float* __restrict__ embeddings, float* __restrict__ out) {
    __shared__ int idx_s[64];
    const int b   = blockIdx.y;
    const int tid = threadIdx.x;
    if (tid < 64) idx_s[tid] = g_indices[b * 64 + tid];
    __syncthreads();

    const int e = blockIdx.x * 256 + tid;
    const unsigned long long AGENT_MASK = (7ULL << 27) | (7ULL << 35) | (7ULL << 43);
    float s = 0.0f, sl = 0.0f;
#pragma unroll
    for (int p = 0; p < 64; p++) {
        float v = embeddings[(size_t)idx_s[p] * EDIM + e];
        s += v;
        if ((AGENT_MASK >> p) & 1ULL) sl += v;
    }
    out[O_ZREAL + (size_t)b * EDIM + e] = s * (1.0f / 64.0f);
    out[O_ZLOC  + (size_t)b * EDIM + e] = sl * (1.0f / 9.0f);
}

// ---------------------------------------------------------------------------
// z_vsa: XOR-sum over 16 CENTRAL patches, threshold > 8.
// ---------------------------------------------------------------------------
__global__ void vsa_kernel(const float* __restrict__ cvsa,
                           const float* __restrict__ proles,
                           float* __restrict__ out) {
    __shared__ int idxc[16];
    const int b   = blockIdx.y;
    const int tid = threadIdx.x;
    if (tid < 16) {
        int p = (2 + (tid >> 2)) * 8 + 2 + (tid & 3);   // CENTRAL[tid]
        idxc[tid] = g_indices[b * 64 + p];
    }
    __syncthreads();

    const int v = blockIdx.x * 256 + tid;
    int cnt = 0;
#pragma unroll
    for (int j = 0; j < 16; j++) {
        int p = (2 + (j >> 2)) * 8 + 2 + (j & 3);
        float cb = cvsa[(size_t)idxc[j] * VDIM + v];
        float pr = proles[(size_t)p * VDIM + v];
        cnt += (cb != pr);
    }
    out[O_ZVSA + (size_t)b * VDIM + v] = (cnt > 8) ? 1.0f : 0.0f;
}

// ---------------------------------------------------------------------------
extern "C" void kernel_launch(void* const* d_in, const int* in_sizes, int n_in,
                              void* d_out, int out_size) {
    const float* pixels     = (const float*)d_in[0];
    const float* codebook   = (const float*)d_in[1];
    const float* embeddings = (const float*)d_in[2];
    const float* cvsa       = (const float*)d_in[3];
    const float* proles     = (const float*)d_in[4];
    float* out = (float*)d_out;

    cudaFuncSetAttribute(argmax_kernel,
                         cudaFuncAttributeMaxDynamicSharedMemorySize, SMEM_BYTES);

    argmax_kernel<<<M_TOTAL / TM, THREADS, SMEM_BYTES>>>(pixels, codebook, out);

    dim3 gm(EDIM / 256, BB);
    means_kernel<<<gm, 256>>>(embeddings, out);

    dim3 gv(VDIM / 256, BB);
    vsa_kernel<<<gv, 256>>>(cvsa, proles, out);
}

// round 16
// speedup vs baseline: 1.5676x; 1.5676x over previous
#include <cuda_runtime.h>
#include <cuda_bf16.h>

// Problem constants
#define BB      1024
#define NPATCH  64
#define PD      192
#define KCODES  4096
#define EDIM    2048
#define VDIM    2048
#define M_TOTAL (BB * NPATCH)   // 65536 patches

// Output layout (concatenated, float32)
#define O_ZREAL 0
#define O_ZVSA  (BB * EDIM)
#define O_IDX   (O_ZVSA + BB * VDIM)
#define O_ZLOC  (O_IDX + BB * NPATCH)

__device__ int g_indices[M_TOTAL];
__device__ __nv_bfloat16 g_cb16[(size_t)KCODES * PD];   // bf16 codebook

// ---------------------------------------------------------------------------
// Strategy: exact argmax via bf16 tensor-core candidate generation + fp32
// rescore with a SOUND error margin.
//   sweep 1: sims in bf16 mma.m16n8k16 -> per-patch bf16 max.
//   sweep 2: recompute identical bf16 sims; every code with
//            sim >= max - (0.0175*||a|| + 1e-5) is rescored in exact fp32
//            (ascending k, strict '>', lowest index on ties).
// Soundness: |bf16dot - fp32dot| <= ||a||*||b||*2^-8 + accum slop
// (Cauchy-Schwarz, codebook rows unit norm); margin > 2E guarantees the
// fp32 argmax is in the candidate set. Expected candidates ~8/patch.
// ---------------------------------------------------------------------------
#define THREADS 512
#define TM 128                    // patches per block (2 images)
#define CODES_PER_TILE 128        // staged codes per smem tile
#define NTILES (KCODES / CODES_PER_TILE)   // 32
#define KSTEPS (PD / 16)          // 12 mma k-steps

#define AS_STRIDE 129             // fp32 As [192][129]
#define AS_FLOATS (PD * AS_STRIDE)          // 24768
#define BS_ROW_U32 100            // bf16 B row: 192 bf16 = 96 u32, pad to 100
#define BS_U32 (CODES_PER_TILE * BS_ROW_U32)   // 12800

// smem layout (bytes): As fp32 | Bs u32 | maxS u32[128] | thrA f32[128] |
//                      normA f32[128] | bestKey u64[128]
#define SMEM_BYTES (AS_FLOATS*4 + BS_U32*4 + 128*4*3 + 128*8)   // 152832

__device__ __forceinline__ unsigned sortable(float x) {
    unsigned b = __float_as_uint(x);
    return b ^ (((unsigned)((int)b >> 31)) | 0x80000000u);
}
__device__ __forceinline__ float unsortable(unsigned s) {
    unsigned b = (s & 0x80000000u) ? (s ^ 0x80000000u) : ~s;
    return __uint_as_float(b);
}
__device__ __forceinline__ unsigned pack_bf16(float lo, float hi) {
    __nv_bfloat162 t = __floats2bfloat162_rn(lo, hi);   // .x = lo (low half)
    return *reinterpret_cast<unsigned*>(&t);
}
__device__ __forceinline__ void mma_bf16(float& c0, float& c1, float& c2, float& c3,
                                         unsigned a0, unsigned a1, unsigned a2, unsigned a3,
                                         unsigned b0, unsigned b1) {
    asm volatile(
        "mma.sync.aligned.m16n8k16.row.col.f32.bf16.bf16.f32 "
        "{%0,%1,%2,%3}, {%4,%5,%6,%7}, {%8,%9}, {%0,%1,%2,%3};\n"
        : "+f"(c0), "+f"(c1), "+f"(c2), "+f"(c3)
        : "r"(a0), "r"(a1), "r"(a2), "r"(a3), "r"(b0), "r"(b1));
}

// Exact fp32 rescore of (patch m, code j); fold into bestKey[m].
// Key = sortable(sim) << 32 | (4095 - j): max sim wins, lower idx on ties.
__device__ __forceinline__ void rescore(const float* __restrict__ As,
                                        const float* __restrict__ cb,
                                        unsigned long long* bestKey,
                                        int m, int j) {
    float s = 0.0f;
#pragma unroll 8
    for (int k = 0; k < PD; k++)
        s = fmaf(As[k * AS_STRIDE + m], cb[(size_t)j * PD + k], s);
    unsigned long long key =
        ((unsigned long long)sortable(s) << 32) | (unsigned)(4095 - j);
    atomicMax(&bestKey[m], key);
}

// ---------------------------------------------------------------------------
__global__ void cvt_cb_kernel(const float* __restrict__ codebook) {
    int i = blockIdx.x * 256 + threadIdx.x;
    if (i < KCODES * PD / 2) {
        float2 v = ((const float2*)codebook)[i];
        ((unsigned*)g_cb16)[i] = pack_bf16(v.x, v.y);
    }
}

// ---------------------------------------------------------------------------
__global__ __launch_bounds__(THREADS, 1)
void argmax_kernel(const float* __restrict__ pixels,
                   const float* __restrict__ codebook,
                   float* __restrict__ out) {
    extern __shared__ float smem[];
    float*    As      = smem;
    unsigned* BsU     = (unsigned*)(smem + AS_FLOATS);
    unsigned* maxS    = BsU + BS_U32;
    float*    thrA    = (float*)(maxS + 128);
    float*    normA   = thrA + 128;
    unsigned long long* bestKey = (unsigned long long*)(normA + 128);

    const int tid  = threadIdx.x;
    const int lane = tid & 31;
    const int w    = tid >> 5;
    const int g    = w & 7;        // patch group (16 patches)
    const int h    = w >> 3;       // code half within staged tile
    const int pb   = blockIdx.x * TM;
    const int b0   = blockIdx.x * 2;
    const unsigned* cb16u = (const unsigned*)g_cb16;

    // ---- Fused patchify: 2 images -> fp32 As[d][p] (k-major, +1 pad).
    {
        const float4* px = (const float4*)(pixels + (size_t)b0 * 3 * 64 * 64);
        for (int i = tid; i < 2 * 3 * 64 * 16; i += THREADS) {
            int img = i / 3072;
            int rem = i - img * 3072;
            int ch  = rem >> 10;
            int r2  = rem & 1023;
            int row = r2 >> 4;
            int col0 = (r2 & 15) << 2;
            float4 v = px[i];
            int p = (img << 6) + ((row >> 3) << 3) + (col0 >> 3);
            int d = (ch << 6) + ((row & 7) << 3) + (col0 & 7);
            As[(d + 0) * AS_STRIDE + p] = v.x;
            As[(d + 1) * AS_STRIDE + p] = v.y;
            As[(d + 2) * AS_STRIDE + p] = v.z;
            As[(d + 3) * AS_STRIDE + p] = v.w;
        }
    }
    __syncthreads();

    // ---- Per-patch norm (for the sound margin) + maxS init.
    if (tid < 128) {
        float s = 0.0f;
#pragma unroll 8
        for (int k = 0; k < PD; k++) {
            float v = As[k * AS_STRIDE + tid];
            s = fmaf(v, v, s);
        }
        normA[tid] = sqrtf(s);
        maxS[tid] = 0u;          // below sortable() of any real
    }

    // ---- Build A fragments once: warp g's 16 patches, all K in registers.
    // m16n8k16 A frag: a0=(m=l/4, k=2(l%4)), a1=m+8, a2=k+8, a3=both.
    unsigned afrag[KSTEPS][4];
    {
        const int gm = g * 16 + (lane >> 2);
        const int kc = 2 * (lane & 3);
#pragma unroll
        for (int ks = 0; ks < KSTEPS; ks++) {
            int k0 = ks * 16 + kc;
            afrag[ks][0] = pack_bf16(As[(k0)     * AS_STRIDE + gm],     As[(k0 + 1) * AS_STRIDE + gm]);
            afrag[ks][1] = pack_bf16(As[(k0)     * AS_STRIDE + gm + 8], As[(k0 + 1) * AS_STRIDE + gm + 8]);
            afrag[ks][2] = pack_bf16(As[(k0 + 8) * AS_STRIDE + gm],     As[(k0 + 9) * AS_STRIDE + gm]);
            afrag[ks][3] = pack_bf16(As[(k0 + 8) * AS_STRIDE + gm + 8], As[(k0 + 9) * AS_STRIDE + gm + 8]);
        }
    }

    // ---- Sweep 1: bf16 max per patch.
    float rm0 = -3.0e38f, rm1 = -3.0e38f;
#pragma unroll 1
    for (int t = 0; t < NTILES; t++) {
        __syncthreads();
        for (int i = tid; i < CODES_PER_TILE * 96; i += THREADS) {
            int r = i / 96, c = i - r * 96;
            BsU[r * BS_ROW_U32 + c] = cb16u[(size_t)(t * CODES_PER_TILE + r) * 96 + c];
        }
        __syncthreads();
        const unsigned* brow0 = BsU + (h * 64 + (lane >> 2)) * BS_ROW_U32 + (lane & 3);
#pragma unroll 1
        for (int nt = 0; nt < 8; nt++) {
            const unsigned* brow = brow0 + nt * 8 * BS_ROW_U32;
            float c0 = 0.f, c1 = 0.f, c2 = 0.f, c3 = 0.f;
#pragma unroll
            for (int ks = 0; ks < KSTEPS; ks++)
                mma_bf16(c0, c1, c2, c3,
                         afrag[ks][0], afrag[ks][1], afrag[ks][2], afrag[ks][3],
                         brow[ks * 8], brow[ks * 8 + 4]);
            rm0 = fmaxf(rm0, fmaxf(c0, c1));
            rm1 = fmaxf(rm1, fmaxf(c2, c3));
        }
    }
    // quad-reduce (lanes sharing the same C-rows) then fold into maxS
#pragma unroll
    for (int off = 1; off <= 2; off <<= 1) {
        rm0 = fmaxf(rm0, __shfl_xor_sync(0xffffffffu, rm0, off));
        rm1 = fmaxf(rm1, __shfl_xor_sync(0xffffffffu, rm1, off));
    }
    if ((lane & 3) == 0) {
        atomicMax(&maxS[g * 16 + (lane >> 2)],     sortable(rm0));
        atomicMax(&maxS[g * 16 + (lane >> 2) + 8], sortable(rm1));
    }
    __syncthreads();

    // ---- Threshold: max - sound margin; init best keys.
    if (tid < 128) {
        float mv = unsortable(maxS[tid]);
        thrA[tid] = mv - (0.0175f * normA[tid] + 1e-5f);
        bestKey[tid] = 0ULL;
    }

    // ---- Sweep 2: recompute (deterministic), rescore candidates in fp32.
#pragma unroll 1
    for (int t = 0; t < NTILES; t++) {
        __syncthreads();
        for (int i = tid; i < CODES_PER_TILE * 96; i += THREADS) {
            int r = i / 96, c = i - r * 96;
            BsU[r * BS_ROW_U32 + c] = cb16u[(size_t)(t * CODES_PER_TILE + r) * 96 + c];
        }
        __syncthreads();
        const unsigned* brow0 = BsU + (h * 64 + (lane >> 2)) * BS_ROW_U32 + (lane & 3);
        const int r0 = g * 16 + (lane >> 2);
        const int r1 = r0 + 8;
        const float th0 = thrA[r0], th1 = thrA[r1];
#pragma unroll 1
        for (int nt = 0; nt < 8; nt++) {
            const unsigned* brow = brow0 + nt * 8 * BS_ROW_U32;
            float c0 = 0.f, c1 = 0.f, c2 = 0.f, c3 = 0.f;
#pragma unroll
            for (int ks = 0; ks < KSTEPS; ks++)
                mma_bf16(c0, c1, c2, c3,
                         afrag[ks][0], afrag[ks][1], afrag[ks][2], afrag[ks][3],
                         brow[ks * 8], brow[ks * 8 + 4]);
            int j0 = t * CODES_PER_TILE + h * 64 + nt * 8 + 2 * (lane & 3);
            if (c0 >= th0) rescore(As, codebook, bestKey, r0, j0);
            if (c1 >= th0) rescore(As, codebook, bestKey, r0, j0 + 1);
            if (c2 >= th1) rescore(As, codebook, bestKey, r1, j0);
            if (c3 >= th1) rescore(As, codebook, bestKey, r1, j0 + 1);
        }
    }
    __syncthreads();

    if (tid < 128) {
        int idx = 4095 - (int)(bestKey[tid] & 0xFFFFFFFFULL);
        g_indices[pb + tid] = idx;
        out[O_IDX + pb + tid] = (float)idx;
    }
}

// ---------------------------------------------------------------------------
__global__ void means_kernel(const float* __restrict__ embeddings, float* __restrict__ out) {
    __shared__ int idx_s[64];
    const int b   = blockIdx.y;
    const int tid = threadIdx.x;
    if (tid < 64) idx_s[tid] = g_indices[b * 64 + tid];
    __syncthreads();

    const int e = blockIdx.x * 256 + tid;
    const unsigned long long AGENT_MASK = (7ULL << 27) | (7ULL << 35) | (7ULL << 43);
    float s = 0.0f, sl = 0.0f;
#pragma unroll
    for (int p = 0; p < 64; p++) {
        float v = embeddings[(size_t)idx_s[p] * EDIM + e];
        s += v;
        if ((AGENT_MASK >> p) & 1ULL) sl += v;
    }
    out[O_ZREAL + (size_t)b * EDIM + e] = s * (1.0f / 64.0f);
    out[O_ZLOC  + (size_t)b * EDIM + e] = sl * (1.0f / 9.0f);
}

// ---------------------------------------------------------------------------
__global__ void vsa_kernel(const float* __restrict__ cvsa,
                           const float* __restrict__ proles,
                           float* __restrict__ out) {
    __shared__ int idxc[16];
    const int b   = blockIdx.y;
    const int tid = threadIdx.x;
    if (tid < 16) {
        int p = (2 + (tid >> 2)) * 8 + 2 + (tid & 3);   // CENTRAL[tid]
        idxc[tid] = g_indices[b * 64 + p];
    }
    __syncthreads();

    const int v = blockIdx.x * 256 + tid;
    int cnt = 0;
#pragma unroll
    for (int j = 0; j < 16; j++) {
        int p = (2 + (j >> 2)) * 8 + 2 + (j & 3);
        float cb = cvsa[(size_t)idxc[j] * VDIM + v];
        float pr = proles[(size_t)p * VDIM + v];
        cnt += (cb != pr);
    }
    out[O_ZVSA + (size_t)b * VDIM + v] = (cnt > 8) ? 1.0f : 0.0f;
}

// ---------------------------------------------------------------------------
extern "C" void kernel_launch(void* const* d_in, const int* in_sizes, int n_in,
                              void* d_out, int out_size) {
    const float* pixels     = (const float*)d_in[0];
    const float* codebook   = (const float*)d_in[1];
    const float* embeddings = (const float*)d_in[2];
    const float* cvsa       = (const float*)d_in[3];
    const float* proles     = (const float*)d_in[4];
    float* out = (float*)d_out;

    cudaFuncSetAttribute(argmax_kernel,
                         cudaFuncAttributeMaxDynamicSharedMemorySize, SMEM_BYTES);

    cvt_cb_kernel<<<(KCODES * PD / 2 + 255) / 256, 256>>>(codebook);

    argmax_kernel<<<M_TOTAL / TM, THREADS, SMEM_BYTES>>>(pixels, codebook, out);

    dim3 gm(EDIM / 256, BB);
    means_kernel<<<gm, 256>>>(embeddings, out);

    dim3 gv(VDIM / 256, BB);
    vsa_kernel<<<gv, 256>>>(cvsa, proles, out);
}